// round 14
// baseline (speedup 1.0000x reference)
#include <cuda_runtime.h>
#include <cuda_fp16.h>
#include <cuda_bf16.h>

#define NN 100000
#define NE 3200000
#define DF 512
#define HID 16
#define NC 7

// gemm1 (tensor core, direct-LDG A): 128 rows per 256-thread block
#define GR   128        // rows per block
#define WSH  24         // Ws stride (halves): 48B rows

// ---------------- scratch (no allocations allowed) ----------------
__device__ float g_deg[NN];
__device__ float g_dinv[NN];
__device__ __align__(16) float g_h1[NN * HID];   // h1s = dinv*(x@W1), plain-stored
__device__ __align__(16) float g_m1[NN * HID];   // sum of h1s[src] over in-edges
__device__ __align__(16) float g_t2[NN * 8];     // t2s = dinv*(h2@W2), padded to 8
__device__ __align__(16) float g_m2[NN * 8];     // sum of t2s[src], padded

// 128-bit global float reduction (sm_90+)
__device__ __forceinline__ void red_add_v4(float* p, float4 v) {
    asm volatile(
        "{\n\t"
        ".reg .u64 pg;\n\t"
        "cvta.to.global.u64 pg, %0;\n\t"
        "red.global.add.v4.f32 [pg], {%1,%2,%3,%4};\n\t"
        "}"
        :: "l"(p), "f"(v.x), "f"(v.y), "f"(v.z), "f"(v.w)
        : "memory");
}

// ---------------- K0: init accumulators ----------------
__global__ void k_init() {
    int i = blockIdx.x * blockDim.x + threadIdx.x;
    float4 z = make_float4(0.f, 0.f, 0.f, 0.f);
    if (i < NN) g_deg[i] = 1.0f;          // self-loop contributes 1 to degree
    if (i < NN * 4) ((float4*)g_m1)[i] = z;
    if (i < NN * 2) ((float4*)g_m2)[i] = z;
}

// ---------------- K1: in-degree ----------------
__global__ void k_deg(const int* __restrict__ ei) {
    int e = blockIdx.x * blockDim.x + threadIdx.x;
    if (e < NE) atomicAdd(&g_deg[ei[NE + e]], 1.0f);
}

// ---------------- K2: dinv ----------------
__global__ void k_dinv() {
    int i = blockIdx.x * blockDim.x + threadIdx.x;
    if (i < NN) g_dinv[i] = rsqrtf(g_deg[i]);   // deg >= 1 always
}

// ---------------- K3: h1s = dinv*(x @ W1), tensor cores, A direct from GMEM -
__global__ __launch_bounds__(256) void k_gemm1(const float* __restrict__ x,
                                               const float* __restrict__ W1) {
    __shared__ __align__(16) __half Ws[DF * WSH];    // 24.6 KB

    int t = threadIdx.x;
    int w = t >> 5, lane = t & 31;
    int row0 = blockIdx.x * GR;

    // stage full W1 (512x16 f32 -> f16), coalesced; 2048 float4, 8 per thread
    #pragma unroll
    for (int i = 0; i < 8; i++) {
        int lin = t + 256 * i;
        int r = lin >> 2, c4 = lin & 3;
        float4 v = *(const float4*)&W1[r * HID + c4 * 4];
        __half2 h0 = __floats2half2_rn(v.x, v.y);
        __half2 h1 = __floats2half2_rn(v.z, v.w);
        uint2 o; o.x = *(unsigned*)&h0; o.y = *(unsigned*)&h1;
        *(uint2*)&Ws[r * WSH + c4 * 4] = o;
    }
    __syncthreads();

    float c[2][4];
    #pragma unroll
    for (int nt = 0; nt < 2; nt++)
        #pragma unroll
        for (int i = 0; i < 4; i++) c[nt][i] = 0.f;

    unsigned ws_u = (unsigned)__cvta_generic_to_shared(&Ws[0]);

    // A fragment coordinates (m16n8k16, row-major): this lane owns
    // rows r0 = g, r1 = g+8 of the warp tile; k-cols cA, cA+1 (and +8).
    int g = lane >> 2;
    int cA = (lane & 3) * 2;
    int r0 = row0 + w * 16 + g;
    int r1 = r0 + 8;
    bool v0 = r0 < NN, v1 = r1 < NN;
    const float* p0 = x + (long)(v0 ? r0 : 0) * DF + cA;
    const float* p1 = x + (long)(v1 ? r1 : 0) * DF + cA;
    float2 z2 = make_float2(0.f, 0.f);
    int klane = lane & 15;

    #pragma unroll 4
    for (int k = 0; k < DF; k += 16) {
        float2 f00 = v0 ? *(const float2*)(p0 + k)     : z2;
        float2 f10 = v1 ? *(const float2*)(p1 + k)     : z2;
        float2 f01 = v0 ? *(const float2*)(p0 + k + 8) : z2;
        float2 f11 = v1 ? *(const float2*)(p1 + k + 8) : z2;
        __half2 ha0 = __floats2half2_rn(f00.x, f00.y);
        __half2 ha1 = __floats2half2_rn(f10.x, f10.y);
        __half2 ha2 = __floats2half2_rn(f01.x, f01.y);
        __half2 ha3 = __floats2half2_rn(f11.x, f11.y);
        unsigned a0 = *(unsigned*)&ha0, a1 = *(unsigned*)&ha1;
        unsigned a2 = *(unsigned*)&ha2, a3 = *(unsigned*)&ha3;

        #pragma unroll
        for (int nt = 0; nt < 2; nt++) {
            unsigned b0, b1;
            unsigned baddr = ws_u + (unsigned)(((k + klane) * WSH + nt * 8) * 2);
            asm volatile("ldmatrix.sync.aligned.m8n8.x2.trans.shared.b16 {%0,%1}, [%2];"
                         : "=r"(b0), "=r"(b1) : "r"(baddr));
            asm volatile("mma.sync.aligned.m16n8k16.row.col.f32.f16.f16.f32 "
                         "{%0,%1,%2,%3}, {%4,%5,%6,%7}, {%8,%9}, {%0,%1,%2,%3};"
                         : "+f"(c[nt][0]), "+f"(c[nt][1]), "+f"(c[nt][2]), "+f"(c[nt][3])
                         : "r"(a0), "r"(a1), "r"(a2), "r"(a3), "r"(b0), "r"(b1));
        }
    }

    // epilogue: scale by dinv, plain store
    int er0 = row0 + w * 16 + (lane >> 2);
    int er1 = er0 + 8;
    int ec = (lane & 3) * 2;
    if (er0 < NN) {
        float dv = g_dinv[er0];
        *(float2*)&g_h1[er0 * HID + 0 + ec] = make_float2(c[0][0] * dv, c[0][1] * dv);
        *(float2*)&g_h1[er0 * HID + 8 + ec] = make_float2(c[1][0] * dv, c[1][1] * dv);
    }
    if (er1 < NN) {
        float dv = g_dinv[er1];
        *(float2*)&g_h1[er1 * HID + 0 + ec] = make_float2(c[0][2] * dv, c[0][3] * dv);
        *(float2*)&g_h1[er1 * HID + 8 + ec] = make_float2(c[1][2] * dv, c[1][3] * dv);
    }
}

// ---------------- K4: layer-1 scatter (4 threads/edge, unweighted) ----------
__global__ void k_scat1(const int* __restrict__ ei) {
    int t = blockIdx.x * blockDim.x + threadIdx.x;
    int e = t >> 2, sub = t & 3;
    if (e >= NE) return;
    int src = ei[e];
    int dst = ei[NE + e];
    float4 h = ((const float4*)g_h1)[src * 4 + sub];
    red_add_v4(&g_m1[dst * HID + sub * 4], h);
}

// ---------------- K5: h2 = relu(dinv*(m1 + h1s) + b1); t2s = dinv*(h2 @ W2) -
__global__ void k_layer2(const float* __restrict__ b1, const float* __restrict__ W2) {
    __shared__ float W2s[HID][8];
    __shared__ float b1s[HID];
    int t = threadIdx.x;
    if (t < HID * NC) W2s[t / NC][t % NC] = W2[t];
    if (t < HID) { W2s[t][7] = 0.0f; b1s[t] = b1[t]; }
    __syncthreads();

    int n = blockIdx.x * blockDim.x + t;
    if (n >= NN) return;
    float dv = g_dinv[n];

    float h[HID];
    #pragma unroll
    for (int j = 0; j < 4; j++) {
        float4 mv = ((const float4*)g_m1)[n * 4 + j];
        float4 hv = ((const float4*)g_h1)[n * 4 + j];
        h[4 * j + 0] = fmaxf(dv * (mv.x + hv.x) + b1s[4 * j + 0], 0.f);
        h[4 * j + 1] = fmaxf(dv * (mv.y + hv.y) + b1s[4 * j + 1], 0.f);
        h[4 * j + 2] = fmaxf(dv * (mv.z + hv.z) + b1s[4 * j + 2], 0.f);
        h[4 * j + 3] = fmaxf(dv * (mv.w + hv.w) + b1s[4 * j + 3], 0.f);
    }

    float o[8];
    #pragma unroll
    for (int c = 0; c < 8; c++) o[c] = 0.f;
    #pragma unroll
    for (int k = 0; k < HID; k++) {
        #pragma unroll
        for (int c = 0; c < 8; c++)
            o[c] += h[k] * W2s[k][c];    // col 7 stays 0
    }
    #pragma unroll
    for (int c = 0; c < 8; c++) o[c] *= dv;   // pre-scale by own dinv
    ((float4*)g_t2)[n * 2 + 0] = make_float4(o[0], o[1], o[2], o[3]);
    ((float4*)g_t2)[n * 2 + 1] = make_float4(o[4], o[5], o[6], o[7]);
}

// ---------------- K6: layer-2 scatter (2 threads/edge, unweighted) ----------
__global__ void k_scat2(const int* __restrict__ ei) {
    int t = blockIdx.x * blockDim.x + threadIdx.x;
    int e = t >> 1, sub = t & 1;
    if (e >= NE) return;
    int src = ei[e];
    int dst = ei[NE + e];
    float4 v = ((const float4*)g_t2)[src * 2 + sub];
    red_add_v4(&g_m2[dst * 8 + sub * 4], v);
}

// ---------------- K7: finalize: logits = dinv*(m2 + t2s) + b2; log_softmax --
__global__ void k_final(const float* __restrict__ b2, float* __restrict__ out) {
    int n = blockIdx.x * blockDim.x + threadIdx.x;
    if (n >= NN) return;
    float dv = g_dinv[n];

    float4 m0 = ((const float4*)g_m2)[n * 2 + 0];
    float4 m1v = ((const float4*)g_m2)[n * 2 + 1];
    float4 t0 = ((const float4*)g_t2)[n * 2 + 0];
    float4 t1 = ((const float4*)g_t2)[n * 2 + 1];

    float l[NC];
    l[0] = dv * (m0.x + t0.x) + b2[0];
    l[1] = dv * (m0.y + t0.y) + b2[1];
    l[2] = dv * (m0.z + t0.z) + b2[2];
    l[3] = dv * (m0.w + t0.w) + b2[3];
    l[4] = dv * (m1v.x + t1.x) + b2[4];
    l[5] = dv * (m1v.y + t1.y) + b2[5];
    l[6] = dv * (m1v.z + t1.z) + b2[6];

    float mx = l[0];
    #pragma unroll
    for (int c = 1; c < NC; c++) mx = fmaxf(mx, l[c]);
    float s = 0.f;
    #pragma unroll
    for (int c = 0; c < NC; c++) s += expf(l[c] - mx);
    float lse = mx + logf(s);
    #pragma unroll
    for (int c = 0; c < NC; c++) out[n * NC + c] = l[c] - lse;
}

// ---------------- launch ----------------
extern "C" void kernel_launch(void* const* d_in, const int* in_sizes, int n_in,
                              void* d_out, int out_size) {
    const float* x   = (const float*)d_in[0];
    const int*   ei  = (const int*)d_in[1];
    const float* W1  = (const float*)d_in[2];
    const float* b1  = (const float*)d_in[3];
    const float* W2  = (const float*)d_in[4];
    const float* b2  = (const float*)d_in[5];
    float*       out = (float*)d_out;

    int gblocks = (NN + GR - 1) / GR;   // 782

    k_init<<<(NN * 4 + 255) / 256, 256>>>();
    k_deg<<<(NE + 255) / 256, 256>>>(ei);
    k_dinv<<<(NN + 255) / 256, 256>>>();
    k_gemm1<<<gblocks, 256>>>(x, W1);
    k_scat1<<<(NE * 4 + 255) / 256, 256>>>(ei);
    k_layer2<<<(NN + 255) / 256, 256>>>(b1, W2);
    k_scat2<<<(NE * 2 + 255) / 256, 256>>>(ei);
    k_final<<<(NN + 255) / 256, 256>>>(b2, out);
}

// round 16
// speedup vs baseline: 1.2000x; 1.2000x over previous
#include <cuda_runtime.h>
#include <cuda_fp16.h>
#include <cuda_bf16.h>

#define NN 100000
#define NE 3200000
#define DF 512
#define HID 16
#define NC 7

// gemm1 (tensor core, cp.async double-buffered): 128 rows per 256-thread block
#define GR   128        // rows per block
#define CK   32         // k per chunk
#define NCH  (DF / CK)  // 16 chunks
#define XST  40         // xs stride (floats): 160B rows, 16B-aligned, conflict-free LDS.64
#define WSH  24         // Ws stride (halves): 48B rows

// ---------------- scratch (no allocations allowed) ----------------
__device__ float g_deg[NN];
__device__ float g_dinv[NN];
__device__ __align__(16) float g_h1[NN * HID];   // h1s = dinv*(x@W1), plain-stored
__device__ __align__(16) float g_m1[NN * HID];   // sum of h1s[src] over in-edges
__device__ __align__(16) float g_t2[NN * 8];     // t2s = dinv*(h2@W2), padded to 8
__device__ __align__(16) float g_m2[NN * 8];     // sum of t2s[src], padded

// 128-bit global float reduction (sm_90+)
__device__ __forceinline__ void red_add_v4(float* p, float4 v) {
    asm volatile(
        "{\n\t"
        ".reg .u64 pg;\n\t"
        "cvta.to.global.u64 pg, %0;\n\t"
        "red.global.add.v4.f32 [pg], {%1,%2,%3,%4};\n\t"
        "}"
        :: "l"(p), "f"(v.x), "f"(v.y), "f"(v.z), "f"(v.w)
        : "memory");
}

// ---------------- K0: init accumulators ----------------
__global__ void k_init() {
    int i = blockIdx.x * blockDim.x + threadIdx.x;
    float4 z = make_float4(0.f, 0.f, 0.f, 0.f);
    if (i < NN) g_deg[i] = 1.0f;          // self-loop contributes 1 to degree
    if (i < NN * 4) ((float4*)g_m1)[i] = z;
    if (i < NN * 2) ((float4*)g_m2)[i] = z;
}

// ---------------- K1: in-degree ----------------
__global__ void k_deg(const int* __restrict__ ei) {
    int e = blockIdx.x * blockDim.x + threadIdx.x;
    if (e < NE) atomicAdd(&g_deg[ei[NE + e]], 1.0f);
}

// ---------------- K2: dinv ----------------
__global__ void k_dinv() {
    int i = blockIdx.x * blockDim.x + threadIdx.x;
    if (i < NN) g_dinv[i] = rsqrtf(g_deg[i]);   // deg >= 1 always
}

// ---------------- K3: h1s = dinv*(x @ W1), tensor cores + cp.async pipeline -
__global__ __launch_bounds__(256) void k_gemm1(const float* __restrict__ x,
                                               const float* __restrict__ W1) {
    __shared__ __align__(16) float  xs[2 * GR * XST];   // 41.0 KB (2 bufs)
    __shared__ __align__(16) __half Ws[DF * WSH];       // 24.6 KB

    int t = threadIdx.x;
    int w = t >> 5, lane = t & 31;
    int row0 = blockIdx.x * GR;

    // stage full W1 (512x16 f32 -> f16), coalesced
    #pragma unroll
    for (int i = 0; i < 8; i++) {
        int lin = t + 256 * i;
        int r = lin >> 2, c4 = lin & 3;
        float4 v = *(const float4*)&W1[r * HID + c4 * 4];
        __half2 h0 = __floats2half2_rn(v.x, v.y);
        __half2 h1 = __floats2half2_rn(v.z, v.w);
        uint2 o; o.x = *(unsigned*)&h0; o.y = *(unsigned*)&h1;
        *(uint2*)&Ws[r * WSH + c4 * 4] = o;
    }

    unsigned xs_u = (unsigned)__cvta_generic_to_shared(&xs[0]);
    unsigned ws_u = (unsigned)__cvta_generic_to_shared(&Ws[0]);

    // stage chunk ch (32 k-cols of 128 rows, raw f32) into buffer buf
    auto stage = [&](int ch, int buf) {
        unsigned base = xs_u + (unsigned)(buf * GR * XST * 4);
        #pragma unroll
        for (int i = 0; i < 4; i++) {
            int seg = t + 256 * i;          // 1024 segments of 16B
            int row = seg >> 3, off = seg & 7;
            int grow = row0 + row;
            const float* src = x + (long)(grow < NN ? grow : 0) * DF + ch * CK + off * 4;
            unsigned dst = base + (unsigned)((row * XST + off * 4) * 4);
            int ss = (grow < NN) ? 16 : 0;  // zero-fill OOB rows
            asm volatile("cp.async.cg.shared.global [%0], [%1], 16, %2;"
                         :: "r"(dst), "l"(src), "r"(ss));
        }
        asm volatile("cp.async.commit_group;");
    };

    stage(0, 0);
    stage(1, 1);

    float c[2][4];
    #pragma unroll
    for (int nt = 0; nt < 2; nt++)
        #pragma unroll
        for (int i = 0; i < 4; i++) c[nt][i] = 0.f;

    int g = lane >> 2;            // fragment row within 8
    int cA = (lane & 3) * 2;      // fragment k-pair col
    int klane = lane & 15;

    for (int ch = 0; ch < NCH; ch++) {
        int buf = ch & 1;
        // DRAIN FIX: last chunk has no younger group behind it -> must wait 0
        if (ch + 1 < NCH) asm volatile("cp.async.wait_group 1;");
        else              asm volatile("cp.async.wait_group 0;");
        __syncthreads();   // chunk `ch` visible to all; W visible on first iter

        const float* xb = &xs[buf * GR * XST];
        #pragma unroll
        for (int kst = 0; kst < CK / 16; kst++) {
            int kk = kst * 16;
            int r0 = (w * 16 + g) * XST + kk + cA;
            float2 f00 = *(const float2*)&xb[r0];
            float2 f10 = *(const float2*)&xb[r0 + 8 * XST];
            float2 f01 = *(const float2*)&xb[r0 + 8];
            float2 f11 = *(const float2*)&xb[r0 + 8 * XST + 8];
            __half2 ha0 = __floats2half2_rn(f00.x, f00.y);
            __half2 ha1 = __floats2half2_rn(f10.x, f10.y);
            __half2 ha2 = __floats2half2_rn(f01.x, f01.y);
            __half2 ha3 = __floats2half2_rn(f11.x, f11.y);
            unsigned a0 = *(unsigned*)&ha0, a1 = *(unsigned*)&ha1;
            unsigned a2 = *(unsigned*)&ha2, a3 = *(unsigned*)&ha3;

            int kabs = ch * CK + kk + klane;
            #pragma unroll
            for (int nt = 0; nt < 2; nt++) {
                unsigned b0, b1;
                unsigned baddr = ws_u + (unsigned)((kabs * WSH + nt * 8) * 2);
                asm volatile("ldmatrix.sync.aligned.m8n8.x2.trans.shared.b16 {%0,%1}, [%2];"
                             : "=r"(b0), "=r"(b1) : "r"(baddr));
                asm volatile("mma.sync.aligned.m16n8k16.row.col.f32.f16.f16.f32 "
                             "{%0,%1,%2,%3}, {%4,%5,%6,%7}, {%8,%9}, {%0,%1,%2,%3};"
                             : "+f"(c[nt][0]), "+f"(c[nt][1]), "+f"(c[nt][2]), "+f"(c[nt][3])
                             : "r"(a0), "r"(a1), "r"(a2), "r"(a3), "r"(b0), "r"(b1));
            }
        }
        __syncthreads();   // everyone done reading buf before overwrite
        if (ch + 2 < NCH) stage(ch + 2, buf);
    }

    // epilogue: scale by dinv, plain store
    int er0 = row0 + w * 16 + g;
    int er1 = er0 + 8;
    if (er0 < NN) {
        float dv = g_dinv[er0];
        *(float2*)&g_h1[er0 * HID + 0 + cA] = make_float2(c[0][0] * dv, c[0][1] * dv);
        *(float2*)&g_h1[er0 * HID + 8 + cA] = make_float2(c[1][0] * dv, c[1][1] * dv);
    }
    if (er1 < NN) {
        float dv = g_dinv[er1];
        *(float2*)&g_h1[er1 * HID + 0 + cA] = make_float2(c[0][2] * dv, c[0][3] * dv);
        *(float2*)&g_h1[er1 * HID + 8 + cA] = make_float2(c[1][2] * dv, c[1][3] * dv);
    }
}

// ---------------- K4: layer-1 scatter (4 threads/edge, unweighted) ----------
__global__ void k_scat1(const int* __restrict__ ei) {
    int t = blockIdx.x * blockDim.x + threadIdx.x;
    int e = t >> 2, sub = t & 3;
    if (e >= NE) return;
    int src = ei[e];
    int dst = ei[NE + e];
    float4 h = ((const float4*)g_h1)[src * 4 + sub];
    red_add_v4(&g_m1[dst * HID + sub * 4], h);
}

// ---------------- K5: h2 = relu(dinv*(m1 + h1s) + b1); t2s = dinv*(h2 @ W2) -
__global__ void k_layer2(const float* __restrict__ b1, const float* __restrict__ W2) {
    __shared__ float W2s[HID][8];
    __shared__ float b1s[HID];
    int t = threadIdx.x;
    if (t < HID * NC) W2s[t / NC][t % NC] = W2[t];
    if (t < HID) { W2s[t][7] = 0.0f; b1s[t] = b1[t]; }
    __syncthreads();

    int n = blockIdx.x * blockDim.x + t;
    if (n >= NN) return;
    float dv = g_dinv[n];

    float h[HID];
    #pragma unroll
    for (int j = 0; j < 4; j++) {
        float4 mv = ((const float4*)g_m1)[n * 4 + j];
        float4 hv = ((const float4*)g_h1)[n * 4 + j];
        h[4 * j + 0] = fmaxf(dv * (mv.x + hv.x) + b1s[4 * j + 0], 0.f);
        h[4 * j + 1] = fmaxf(dv * (mv.y + hv.y) + b1s[4 * j + 1], 0.f);
        h[4 * j + 2] = fmaxf(dv * (mv.z + hv.z) + b1s[4 * j + 2], 0.f);
        h[4 * j + 3] = fmaxf(dv * (mv.w + hv.w) + b1s[4 * j + 3], 0.f);
    }

    float o[8];
    #pragma unroll
    for (int c = 0; c < 8; c++) o[c] = 0.f;
    #pragma unroll
    for (int k = 0; k < HID; k++) {
        #pragma unroll
        for (int c = 0; c < 8; c++)
            o[c] += h[k] * W2s[k][c];    // col 7 stays 0
    }
    #pragma unroll
    for (int c = 0; c < 8; c++) o[c] *= dv;   // pre-scale by own dinv
    ((float4*)g_t2)[n * 2 + 0] = make_float4(o[0], o[1], o[2], o[3]);
    ((float4*)g_t2)[n * 2 + 1] = make_float4(o[4], o[5], o[6], o[7]);
}

// ---------------- K6: layer-2 scatter (2 threads/edge, unweighted) ----------
__global__ void k_scat2(const int* __restrict__ ei) {
    int t = blockIdx.x * blockDim.x + threadIdx.x;
    int e = t >> 1, sub = t & 1;
    if (e >= NE) return;
    int src = ei[e];
    int dst = ei[NE + e];
    float4 v = ((const float4*)g_t2)[src * 2 + sub];
    red_add_v4(&g_m2[dst * 8 + sub * 4], v);
}

// ---------------- K7: finalize: logits = dinv*(m2 + t2s) + b2; log_softmax --
__global__ void k_final(const float* __restrict__ b2, float* __restrict__ out) {
    int n = blockIdx.x * blockDim.x + threadIdx.x;
    if (n >= NN) return;
    float dv = g_dinv[n];

    float4 m0 = ((const float4*)g_m2)[n * 2 + 0];
    float4 m1v = ((const float4*)g_m2)[n * 2 + 1];
    float4 t0 = ((const float4*)g_t2)[n * 2 + 0];
    float4 t1 = ((const float4*)g_t2)[n * 2 + 1];

    float l[NC];
    l[0] = dv * (m0.x + t0.x) + b2[0];
    l[1] = dv * (m0.y + t0.y) + b2[1];
    l[2] = dv * (m0.z + t0.z) + b2[2];
    l[3] = dv * (m0.w + t0.w) + b2[3];
    l[4] = dv * (m1v.x + t1.x) + b2[4];
    l[5] = dv * (m1v.y + t1.y) + b2[5];
    l[6] = dv * (m1v.z + t1.z) + b2[6];

    float mx = l[0];
    #pragma unroll
    for (int c = 1; c < NC; c++) mx = fmaxf(mx, l[c]);
    float s = 0.f;
    #pragma unroll
    for (int c = 0; c < NC; c++) s += expf(l[c] - mx);
    float lse = mx + logf(s);
    #pragma unroll
    for (int c = 0; c < NC; c++) out[n * NC + c] = l[c] - lse;
}

// ---------------- launch ----------------
extern "C" void kernel_launch(void* const* d_in, const int* in_sizes, int n_in,
                              void* d_out, int out_size) {
    const float* x   = (const float*)d_in[0];
    const int*   ei  = (const int*)d_in[1];
    const float* W1  = (const float*)d_in[2];
    const float* b1  = (const float*)d_in[3];
    const float* W2  = (const float*)d_in[4];
    const float* b2  = (const float*)d_in[5];
    float*       out = (float*)d_out;

    int gblocks = (NN + GR - 1) / GR;   // 782

    k_init<<<(NN * 4 + 255) / 256, 256>>>();
    k_deg<<<(NE + 255) / 256, 256>>>(ei);
    k_dinv<<<(NN + 255) / 256, 256>>>();
    k_gemm1<<<gblocks, 256>>>(x, W1);
    k_scat1<<<(NE * 4 + 255) / 256, 256>>>(ei);
    k_layer2<<<(NN + 255) / 256, 256>>>(b1, W2);
    k_scat2<<<(NE * 2 + 255) / 256, 256>>>(ei);
    k_final<<<(NN + 255) / 256, 256>>>(b2, out);
}

// round 17
// speedup vs baseline: 1.2161x; 1.0134x over previous
#include <cuda_runtime.h>
#include <cuda_fp16.h>
#include <cuda_bf16.h>

#define NN 100000
#define NE 3200000
#define DF 512
#define HID 16
#define NC 7

// gemm1 (tensor core, cp.async double-buffered): 128 rows per 256-thread block
#define GR   128
#define CK   32
#define NCH  (DF / CK)
#define XST  40
#define WSH  24

// ---------------- scratch (no allocations allowed) ----------------
__device__ int   g_cnt[NN];                      // in-degree (excl self)
__device__ int   g_base[NN];                     // CSR offsets
__device__ int   g_cur[NN];                      // fill cursors
__device__ int   g_csr[NE];                      // src list bucketed by dst
__device__ int   g_total;
__device__ float g_dinv[NN];
__device__ __align__(16) float g_h1[NN * HID];   // h1s = dinv*(x@W1)
__device__ __align__(16) float g_t2[NN * 8];     // t2s = dinv*(h2@W2), padded

// ---------------- K0: init ----------------
__global__ void k_init() {
    int i = blockIdx.x * blockDim.x + threadIdx.x;
    if (i < NN) g_cnt[i] = 0;
    if (i == 0) g_total = 0;
}

// ---------------- K1: in-degree histogram ----------------
__global__ void k_hist(const int* __restrict__ ei) {
    int e = blockIdx.x * blockDim.x + threadIdx.x;
    if (e < NE) atomicAdd(&g_cnt[ei[NE + e]], 1);
}

// ---------------- K2: warp-aggregated offset alloc + dinv ----------------
__global__ void k_alloc() {
    int n = blockIdx.x * blockDim.x + threadIdx.x;
    int lane = threadIdx.x & 31;
    int c = (n < NN) ? g_cnt[n] : 0;
    // inclusive warp scan
    int x = c;
    #pragma unroll
    for (int d = 1; d < 32; d <<= 1) {
        int y = __shfl_up_sync(0xffffffffu, x, d);
        if (lane >= d) x += y;
    }
    int excl = x - c;
    int total = __shfl_sync(0xffffffffu, x, 31);
    int base0 = 0;
    if (lane == 31) base0 = atomicAdd(&g_total, total);
    base0 = __shfl_sync(0xffffffffu, base0, 31);
    if (n < NN) {
        g_base[n] = base0 + excl;
        g_cur[n]  = base0 + excl;
        g_dinv[n] = rsqrtf((float)c + 1.0f);
    }
}

// ---------------- K3: CSR fill ----------------
__global__ void k_fill(const int* __restrict__ ei) {
    int e = blockIdx.x * blockDim.x + threadIdx.x;
    if (e >= NE) return;
    int dst = ei[NE + e];
    int src = ei[e];
    int pos = atomicAdd(&g_cur[dst], 1);
    g_csr[pos] = src;
}

// ---------------- K4: h1s = dinv*(x @ W1), tensor cores + cp.async (R16) ----
__global__ __launch_bounds__(256) void k_gemm1(const float* __restrict__ x,
                                               const float* __restrict__ W1) {
    __shared__ __align__(16) float  xs[2 * GR * XST];
    __shared__ __align__(16) __half Ws[DF * WSH];

    int t = threadIdx.x;
    int w = t >> 5, lane = t & 31;
    int row0 = blockIdx.x * GR;

    #pragma unroll
    for (int i = 0; i < 8; i++) {
        int lin = t + 256 * i;
        int r = lin >> 2, c4 = lin & 3;
        float4 v = *(const float4*)&W1[r * HID + c4 * 4];
        __half2 h0 = __floats2half2_rn(v.x, v.y);
        __half2 h1 = __floats2half2_rn(v.z, v.w);
        uint2 o; o.x = *(unsigned*)&h0; o.y = *(unsigned*)&h1;
        *(uint2*)&Ws[r * WSH + c4 * 4] = o;
    }

    unsigned xs_u = (unsigned)__cvta_generic_to_shared(&xs[0]);
    unsigned ws_u = (unsigned)__cvta_generic_to_shared(&Ws[0]);

    auto stage = [&](int ch, int buf) {
        unsigned base = xs_u + (unsigned)(buf * GR * XST * 4);
        #pragma unroll
        for (int i = 0; i < 4; i++) {
            int seg = t + 256 * i;
            int row = seg >> 3, off = seg & 7;
            int grow = row0 + row;
            const float* src = x + (long)(grow < NN ? grow : 0) * DF + ch * CK + off * 4;
            unsigned dst = base + (unsigned)((row * XST + off * 4) * 4);
            int ss = (grow < NN) ? 16 : 0;
            asm volatile("cp.async.cg.shared.global [%0], [%1], 16, %2;"
                         :: "r"(dst), "l"(src), "r"(ss));
        }
        asm volatile("cp.async.commit_group;");
    };

    stage(0, 0);
    stage(1, 1);

    float c[2][4];
    #pragma unroll
    for (int nt = 0; nt < 2; nt++)
        #pragma unroll
        for (int i = 0; i < 4; i++) c[nt][i] = 0.f;

    int g = lane >> 2;
    int cA = (lane & 3) * 2;
    int klane = lane & 15;

    for (int ch = 0; ch < NCH; ch++) {
        int buf = ch & 1;
        if (ch + 1 < NCH) asm volatile("cp.async.wait_group 1;");
        else              asm volatile("cp.async.wait_group 0;");
        __syncthreads();

        const float* xb = &xs[buf * GR * XST];
        #pragma unroll
        for (int kst = 0; kst < CK / 16; kst++) {
            int kk = kst * 16;
            int r0 = (w * 16 + g) * XST + kk + cA;
            float2 f00 = *(const float2*)&xb[r0];
            float2 f10 = *(const float2*)&xb[r0 + 8 * XST];
            float2 f01 = *(const float2*)&xb[r0 + 8];
            float2 f11 = *(const float2*)&xb[r0 + 8 * XST + 8];
            __half2 ha0 = __floats2half2_rn(f00.x, f00.y);
            __half2 ha1 = __floats2half2_rn(f10.x, f10.y);
            __half2 ha2 = __floats2half2_rn(f01.x, f01.y);
            __half2 ha3 = __floats2half2_rn(f11.x, f11.y);
            unsigned a0 = *(unsigned*)&ha0, a1 = *(unsigned*)&ha1;
            unsigned a2 = *(unsigned*)&ha2, a3 = *(unsigned*)&ha3;

            int kabs = ch * CK + kk + klane;
            #pragma unroll
            for (int nt = 0; nt < 2; nt++) {
                unsigned b0, b1;
                unsigned baddr = ws_u + (unsigned)((kabs * WSH + nt * 8) * 2);
                asm volatile("ldmatrix.sync.aligned.m8n8.x2.trans.shared.b16 {%0,%1}, [%2];"
                             : "=r"(b0), "=r"(b1) : "r"(baddr));
                asm volatile("mma.sync.aligned.m16n8k16.row.col.f32.f16.f16.f32 "
                             "{%0,%1,%2,%3}, {%4,%5,%6,%7}, {%8,%9}, {%0,%1,%2,%3};"
                             : "+f"(c[nt][0]), "+f"(c[nt][1]), "+f"(c[nt][2]), "+f"(c[nt][3])
                             : "r"(a0), "r"(a1), "r"(a2), "r"(a3), "r"(b0), "r"(b1));
            }
        }
        __syncthreads();
        if (ch + 2 < NCH) stage(ch + 2, buf);
    }

    int er0 = row0 + w * 16 + g;
    int er1 = er0 + 8;
    if (er0 < NN) {
        float dv = g_dinv[er0];
        *(float2*)&g_h1[er0 * HID + 0 + cA] = make_float2(c[0][0] * dv, c[0][1] * dv);
        *(float2*)&g_h1[er0 * HID + 8 + cA] = make_float2(c[1][0] * dv, c[1][1] * dv);
    }
    if (er1 < NN) {
        float dv = g_dinv[er1];
        *(float2*)&g_h1[er1 * HID + 0 + cA] = make_float2(c[0][2] * dv, c[0][3] * dv);
        *(float2*)&g_h1[er1 * HID + 8 + cA] = make_float2(c[1][2] * dv, c[1][3] * dv);
    }
}

// ---------------- K5: gather layer1 + fused layer2 (4 threads/node) ---------
__global__ void k_gather1(const float* __restrict__ b1, const float* __restrict__ W2) {
    __shared__ float W2s[HID][8];
    __shared__ float b1s[HID];
    int t = threadIdx.x;
    if (t < HID * NC) W2s[t / NC][t % NC] = W2[t];
    if (t < HID) { W2s[t][7] = 0.0f; b1s[t] = b1[t]; }
    __syncthreads();

    int gid = blockIdx.x * blockDim.x + t;
    int node = gid >> 2, sub = gid & 3;
    if (node >= NN) node = NN - 1;   // clamp: dup groups recompute same value

    int base = g_base[node];
    int cnt  = g_cnt[node];
    const float4* h1v = (const float4*)g_h1;

    float4 acc = h1v[node * 4 + sub];   // self-loop term
    float4 acc2 = make_float4(0.f, 0.f, 0.f, 0.f);
    int i = base, end = base + cnt;
    for (; i + 1 < end; i += 2) {
        int s0 = g_csr[i], s1 = g_csr[i + 1];
        float4 a = h1v[s0 * 4 + sub];
        float4 b = h1v[s1 * 4 + sub];
        acc.x += a.x; acc.y += a.y; acc.z += a.z; acc.w += a.w;
        acc2.x += b.x; acc2.y += b.y; acc2.z += b.z; acc2.w += b.w;
    }
    if (i < end) {
        int s0 = g_csr[i];
        float4 a = h1v[s0 * 4 + sub];
        acc.x += a.x; acc.y += a.y; acc.z += a.z; acc.w += a.w;
    }
    acc.x += acc2.x; acc.y += acc2.y; acc.z += acc2.z; acc.w += acc2.w;

    float dv = g_dinv[node];
    float h[4];
    h[0] = fmaxf(dv * acc.x + b1s[sub * 4 + 0], 0.f);
    h[1] = fmaxf(dv * acc.y + b1s[sub * 4 + 1], 0.f);
    h[2] = fmaxf(dv * acc.z + b1s[sub * 4 + 2], 0.f);
    h[3] = fmaxf(dv * acc.w + b1s[sub * 4 + 3], 0.f);

    float o[8];
    #pragma unroll
    for (int c = 0; c < 8; c++) o[c] = 0.f;
    #pragma unroll
    for (int k = 0; k < 4; k++)
        #pragma unroll
        for (int c = 0; c < 8; c++)
            o[c] += h[k] * W2s[sub * 4 + k][c];

    // reduce across the 4 lanes of this node (lane groups 4-aligned, all active)
    #pragma unroll
    for (int d = 1; d < 4; d <<= 1)
        #pragma unroll
        for (int c = 0; c < 8; c++)
            o[c] += __shfl_xor_sync(0xffffffffu, o[c], d);

    if (sub == 0) {
        #pragma unroll
        for (int c = 0; c < 8; c++) o[c] *= dv;   // t2s = dinv * t2
        ((float4*)g_t2)[node * 2 + 0] = make_float4(o[0], o[1], o[2], o[3]);
        ((float4*)g_t2)[node * 2 + 1] = make_float4(o[4], o[5], o[6], o[7]);
    }
}

// ---------------- K6: gather layer2 + fused log_softmax (2 threads/node) ----
__global__ void k_gather2(const float* __restrict__ b2, float* __restrict__ out) {
    int gid = blockIdx.x * blockDim.x + threadIdx.x;
    int node = gid >> 1, sub = gid & 1;
    if (node >= NN) node = NN - 1;   // clamp (dup write same value)

    int base = g_base[node];
    int cnt  = g_cnt[node];
    const float4* t2v = (const float4*)g_t2;

    float4 acc = t2v[node * 2 + sub];   // self-loop term
    float4 acc2 = make_float4(0.f, 0.f, 0.f, 0.f);
    int i = base, end = base + cnt;
    for (; i + 1 < end; i += 2) {
        int s0 = g_csr[i], s1 = g_csr[i + 1];
        float4 a = t2v[s0 * 2 + sub];
        float4 b = t2v[s1 * 2 + sub];
        acc.x += a.x; acc.y += a.y; acc.z += a.z; acc.w += a.w;
        acc2.x += b.x; acc2.y += b.y; acc2.z += b.z; acc2.w += b.w;
    }
    if (i < end) {
        int s0 = g_csr[i];
        float4 a = t2v[s0 * 2 + sub];
        acc.x += a.x; acc.y += a.y; acc.z += a.z; acc.w += a.w;
    }
    acc.x += acc2.x; acc.y += acc2.y; acc.z += acc2.z; acc.w += acc2.w;

    // exchange halves between the 2 lanes of this node (pairs 2-aligned)
    float4 other;
    other.x = __shfl_xor_sync(0xffffffffu, acc.x, 1);
    other.y = __shfl_xor_sync(0xffffffffu, acc.y, 1);
    other.z = __shfl_xor_sync(0xffffffffu, acc.z, 1);
    other.w = __shfl_xor_sync(0xffffffffu, acc.w, 1);

    if (sub == 0) {
        float dv = g_dinv[node];
        float l[NC];
        l[0] = dv * acc.x + b2[0];
        l[1] = dv * acc.y + b2[1];
        l[2] = dv * acc.z + b2[2];
        l[3] = dv * acc.w + b2[3];
        l[4] = dv * other.x + b2[4];
        l[5] = dv * other.y + b2[5];
        l[6] = dv * other.z + b2[6];

        float mx = l[0];
        #pragma unroll
        for (int c = 1; c < NC; c++) mx = fmaxf(mx, l[c]);
        float s = 0.f;
        #pragma unroll
        for (int c = 0; c < NC; c++) s += expf(l[c] - mx);
        float lse = mx + logf(s);
        #pragma unroll
        for (int c = 0; c < NC; c++) out[node * NC + c] = l[c] - lse;
    }
}

// ---------------- launch ----------------
extern "C" void kernel_launch(void* const* d_in, const int* in_sizes, int n_in,
                              void* d_out, int out_size) {
    const float* x   = (const float*)d_in[0];
    const int*   ei  = (const int*)d_in[1];
    const float* W1  = (const float*)d_in[2];
    const float* b1  = (const float*)d_in[3];
    const float* W2  = (const float*)d_in[4];
    const float* b2  = (const float*)d_in[5];
    float*       out = (float*)d_out;

    int gblocks = (NN + GR - 1) / GR;   // 782

    k_init<<<(NN + 255) / 256, 256>>>();
    k_hist<<<(NE + 255) / 256, 256>>>(ei);
    k_alloc<<<(NN + 255) / 256, 256>>>();
    k_fill<<<(NE + 255) / 256, 256>>>(ei);
    k_gemm1<<<gblocks, 256>>>(x, W1);
    k_gather1<<<(NN * 4 + 255) / 256, 256>>>(b1, W2);
    k_gather2<<<(NN * 2 + 255) / 256, 256>>>(b2, out);
}